// round 2
// baseline (speedup 1.0000x reference)
#include <cuda_runtime.h>
#include <cuda_bf16.h>

#define THREADS 256
#define ITERS   8
// elements per CTA = THREADS * 4 * ITERS = 8192 floats

__global__ __launch_bounds__(THREADS, 6) void nf4_quant_kernel(
    const float* __restrict__ w,
    const float* __restrict__ log_scale,
    float* __restrict__ out,
    int n4)                      // total float4 count
{
    // Integer domain: u = rne((v+1)*2^22) obtained as low-24 bits of
    // fma(v, 2^22, 3*2^22) for v in [-1,1].  Cell j = (u + 2^12) >> 13, j in [0,1024].
    // Each cell holds <=1 NF4 midpoint (cell width 2^13 in u-units << min mid gap ~357K).
    //
    // tbl[j]    : packed [ m0_int:24 | lo_idx:4 | hi_idx:4 ]
    //             m0_int = rne((mid+1)*2^22) via the SAME fma -> (u > m0_int) == (v > mid)
    //             exactly, except when u == m0_int (ambiguous rounding bucket).
    // midtbl[j] : exact fp32 midpoint for the rare ambiguous case (2.0f sentinel).
    // lvlrep    : NF4 levels replicated per lane -> conflict-free LDS.32.
    __shared__ unsigned tbl[1025];
    __shared__ float    midtbl[1025];
    __shared__ float    lvlrep[16 * 32];

    {
        const float nf4[16] = {
            -1.0f, -0.6961928f, -0.52507305f, -0.39491749f, -0.28444138f,
            -0.18477343f, -0.09105004f, 0.0f, 0.0795803f, 0.1609302f,
            0.2461123f, 0.33791524f, 0.44070983f, 0.562617f, 0.72295684f, 1.0f};

        for (int t = threadIdx.x; t < 16 * 32; t += THREADS)
            lvlrep[t] = nf4[t >> 5];

        for (int t = threadIdx.x; t < 1025; t += THREADS) {
            const int cell_lo = t * 8192 - 4096;
            const int cell_hi = cell_lo + 8192;
            int      b     = 0;
            unsigned m0    = 0;
            float    midf  = 2.0f;      // sentinel: v <= 1 < 2 -> picks lo (lo==hi there)
            bool     found = false;
            #pragma unroll
            for (int k = 0; k < 15; k++) {
                float mid = 0.5f * (nf4[k] + nf4[k + 1]);
                int U = (int)(__float_as_uint(fmaf(mid, 4194304.0f, 12582912.0f)) & 0xFFFFFFu);
                if (U < cell_lo)      b++;
                else if (U < cell_hi) { m0 = (unsigned)U; midf = mid; found = true; }
            }
            unsigned lo = (unsigned)b;
            unsigned hi = found ? (unsigned)(b + 1) : (unsigned)b;
            tbl[t]    = (m0 << 8) | (lo << 4) | hi;
            midtbl[t] = midf;
        }
    }
    __syncthreads();

    const float e = expf(__ldg(log_scale));
    const unsigned laneOff = (threadIdx.x & 31u) * 4u;   // byte offset into lvlrep row

    const float4* __restrict__ w4 = (const float4*)w;
    float4* __restrict__       o4 = (float4*)out;

    const int base = blockIdx.x * (THREADS * ITERS) + threadIdx.x;

    float4 cur = make_float4(0.f, 0.f, 0.f, 0.f);
    if (base < n4) cur = w4[base];

    #pragma unroll
    for (int i = 0; i < ITERS; i++) {
        const int idx = base + i * THREADS;
        float4 nxt = make_float4(0.f, 0.f, 0.f, 0.f);
        if (i + 1 < ITERS) {
            int nidx = idx + THREADS;
            if (nidx < n4) nxt = w4[nidx];
        }

        // block absmax over 64 consecutive floats = 16 consecutive lanes x float4
        float m = fmaxf(fmaxf(fabsf(cur.x), fabsf(cur.y)),
                        fmaxf(fabsf(cur.z), fabsf(cur.w)));
        m = fmaxf(m, __shfl_xor_sync(0xffffffffu, m, 1));
        m = fmaxf(m, __shfl_xor_sync(0xffffffffu, m, 2));
        m = fmaxf(m, __shfl_xor_sync(0xffffffffu, m, 4));
        m = fmaxf(m, __shfl_xor_sync(0xffffffffu, m, 8));

        const float scale = fmaxf(m * e, 1e-6f);
        const float inv   = 1.0f / scale;

        float4 r;
        {
            float vx = fminf(fmaxf(cur.x * inv, -1.0f), 1.0f);
            float vy = fminf(fmaxf(cur.y * inv, -1.0f), 1.0f);
            float vz = fminf(fmaxf(cur.z * inv, -1.0f), 1.0f);
            float vw = fminf(fmaxf(cur.w * inv, -1.0f), 1.0f);

            unsigned ux = __float_as_uint(fmaf(vx, 4194304.0f, 12582912.0f)) & 0xFFFFFFu;
            unsigned uy = __float_as_uint(fmaf(vy, 4194304.0f, 12582912.0f)) & 0xFFFFFFu;
            unsigned uz = __float_as_uint(fmaf(vz, 4194304.0f, 12582912.0f)) & 0xFFFFFFu;
            unsigned uw = __float_as_uint(fmaf(vw, 4194304.0f, 12582912.0f)) & 0xFFFFFFu;

            unsigned jx = (ux + 4096u) >> 13;
            unsigned jy = (uy + 4096u) >> 13;
            unsigned jz = (uz + 4096u) >> 13;
            unsigned jw = (uw + 4096u) >> 13;

            unsigned ex = tbl[jx];
            unsigned ey = tbl[jy];
            unsigned ez = tbl[jz];
            unsigned ew = tbl[jw];

            unsigned m0x = ex >> 8, m0y = ey >> 8, m0z = ez >> 8, m0w = ew >> 8;

            bool gx, gy, gz, gw;
            // exact path: u != m0 -> integer compare is exactly (v > mid);
            // ambiguous bucket (u == m0, ~1e-6 of elements) -> exact fp32 compare.
            if (ux != m0x) gx = (ux > m0x); else gx = (vx > midtbl[jx]);
            if (uy != m0y) gy = (uy > m0y); else gy = (vy > midtbl[jy]);
            if (uz != m0z) gz = (uz > m0z); else gz = (vz > midtbl[jz]);
            if (uw != m0w) gw = (uw > m0w); else gw = (vw > midtbl[jw]);

            unsigned ix = (ex >> (gx ? 0 : 4)) & 0xFu;
            unsigned iy = (ey >> (gy ? 0 : 4)) & 0xFu;
            unsigned iz = (ez >> (gz ? 0 : 4)) & 0xFu;
            unsigned iw = (ew >> (gw ? 0 : 4)) & 0xFu;

            const float* lvlb = (const float*)((const char*)lvlrep + laneOff);
            r.x = lvlb[ix * 32] * scale;
            r.y = lvlb[iy * 32] * scale;
            r.z = lvlb[iz * 32] * scale;
            r.w = lvlb[iw * 32] * scale;
        }

        if (idx < n4) o4[idx] = r;
        cur = nxt;
    }
}

extern "C" void kernel_launch(void* const* d_in, const int* in_sizes, int n_in,
                              void* d_out, int out_size)
{
    const float* w  = (const float*)d_in[0];
    const float* ls = (const float*)d_in[1];
    float* out      = (float*)d_out;

    const int n  = in_sizes[0];          // 8192*8192, divisible by 64
    const int n4 = n >> 2;               // float4 count
    const int elemsPerCta = THREADS * ITERS;
    const int grid = (n4 + elemsPerCta - 1) / elemsPerCta;

    nf4_quant_kernel<<<grid, THREADS>>>(w, ls, out, n4);
}

// round 3
// speedup vs baseline: 1.2246x; 1.2246x over previous
#include <cuda_runtime.h>
#include <cuda_bf16.h>

#define THREADS 256
#define ITERS   8
// elements per CTA = THREADS * 4 * ITERS = 8192 floats

__global__ __launch_bounds__(THREADS) void nf4_quant_kernel(
    const float* __restrict__ w,
    const float* __restrict__ log_scale,
    float* __restrict__ out,
    int n4)                      // total float4 count
{
    // Cell map: j = rne(v*512) + 512 in [0,1024], obtained as low bits of
    // fma(v, 512, 512 + 2^23).  Cell width 1/512 << min NF4-midpoint gap 0.085,
    // so each cell contains at most one midpoint.
    //
    // tbl_b[j]  : uint8 = #midpoints whose cell index < j  (bin base index)
    // thr_rep   : thr_rep[b*32+lane] = MID[b] (2.0 sentinel for b=15), lane-replicated
    //             -> conflict-free LDS.  idx = b + (v > MID[b])  == searchsorted exact.
    // lvl_rep   : lvl_rep[i*32+lane] = NF4[i], lane-replicated -> conflict-free LDS.
    __shared__ unsigned char tbl_b[1056];
    __shared__ float thr_rep[16 * 32];
    __shared__ float lvl_rep[16 * 32];

    {
        const float nf4[16] = {
            -1.0f, -0.6961928f, -0.52507305f, -0.39491749f, -0.28444138f,
            -0.18477343f, -0.09105004f, 0.0f, 0.0795803f, 0.1609302f,
            0.2461123f, 0.33791524f, 0.44070983f, 0.562617f, 0.72295684f, 1.0f};

        for (int t = threadIdx.x; t < 16 * 32; t += THREADS) {
            int b = t >> 5;
            lvl_rep[t] = nf4[b];
            thr_rep[t] = (b < 15) ? 0.5f * (nf4[b] + nf4[b + 1]) : 2.0f;
        }

        for (int j = threadIdx.x; j < 1056; j += THREADS) {
            int cnt = 0;
            #pragma unroll
            for (int k = 0; k < 15; k++) {
                float mid = 0.5f * (nf4[k] + nf4[k + 1]);
                int jm = (int)(__float_as_uint(fmaf(mid, 512.0f, 8389120.0f)) & 0x7FFu);
                if (jm < j) cnt++;
            }
            tbl_b[j] = (unsigned char)cnt;
        }
    }
    __syncthreads();

    const float e = expf(__ldg(log_scale));
    const unsigned lane = threadIdx.x & 31u;
    const float* __restrict__ thr_lane = thr_rep + lane;
    const float* __restrict__ lvl_lane = lvl_rep + lane;

    const float4* __restrict__ w4 = (const float4*)w;
    float4* __restrict__       o4 = (float4*)out;

    const int base = blockIdx.x * (THREADS * ITERS) + threadIdx.x;

    float4 cur = make_float4(0.f, 0.f, 0.f, 0.f);
    if (base < n4) cur = __ldcs(&w4[base]);

    #pragma unroll
    for (int i = 0; i < ITERS; i++) {
        const int idx = base + i * THREADS;
        float4 nxt = make_float4(0.f, 0.f, 0.f, 0.f);
        if (i + 1 < ITERS) {
            int nidx = idx + THREADS;
            if (nidx < n4) nxt = __ldcs(&w4[nidx]);
        }

        // block absmax over 64 consecutive floats = 16 consecutive lanes x float4
        float m = fmaxf(fmaxf(fabsf(cur.x), fabsf(cur.y)),
                        fmaxf(fabsf(cur.z), fabsf(cur.w)));
        m = fmaxf(m, __shfl_xor_sync(0xffffffffu, m, 1));
        m = fmaxf(m, __shfl_xor_sync(0xffffffffu, m, 2));
        m = fmaxf(m, __shfl_xor_sync(0xffffffffu, m, 4));
        m = fmaxf(m, __shfl_xor_sync(0xffffffffu, m, 8));

        const float scale = fmaxf(m * e, 1e-6f);
        const float inv   = 1.0f / scale;

        float4 r;
        {
            float vx = fminf(fmaxf(cur.x * inv, -1.0f), 1.0f);
            float vy = fminf(fmaxf(cur.y * inv, -1.0f), 1.0f);
            float vz = fminf(fmaxf(cur.z * inv, -1.0f), 1.0f);
            float vw = fminf(fmaxf(cur.w * inv, -1.0f), 1.0f);

            unsigned jx = __float_as_uint(fmaf(vx, 512.0f, 8389120.0f)) & 0x7FFu;
            unsigned jy = __float_as_uint(fmaf(vy, 512.0f, 8389120.0f)) & 0x7FFu;
            unsigned jz = __float_as_uint(fmaf(vz, 512.0f, 8389120.0f)) & 0x7FFu;
            unsigned jw = __float_as_uint(fmaf(vw, 512.0f, 8389120.0f)) & 0x7FFu;

            unsigned bx = tbl_b[jx];
            unsigned by = tbl_b[jy];
            unsigned bz = tbl_b[jz];
            unsigned bw = tbl_b[jw];

            float tx = thr_lane[bx * 32u];
            float ty = thr_lane[by * 32u];
            float tz = thr_lane[bz * 32u];
            float tw = thr_lane[bw * 32u];

            bx += (vx > tx);
            by += (vy > ty);
            bz += (vz > tz);
            bw += (vw > tw);

            r.x = lvl_lane[bx * 32u] * scale;
            r.y = lvl_lane[by * 32u] * scale;
            r.z = lvl_lane[bz * 32u] * scale;
            r.w = lvl_lane[bw * 32u] * scale;
        }

        if (idx < n4) __stcs(&o4[idx], r);
        cur = nxt;
    }
}

extern "C" void kernel_launch(void* const* d_in, const int* in_sizes, int n_in,
                              void* d_out, int out_size)
{
    const float* w  = (const float*)d_in[0];
    const float* ls = (const float*)d_in[1];
    float* out      = (float*)d_out;

    const int n  = in_sizes[0];          // 8192*8192, divisible by 64
    const int n4 = n >> 2;               // float4 count
    const int elemsPerCta = THREADS * ITERS;
    const int grid = (n4 + elemsPerCta - 1) / elemsPerCta;

    nf4_quant_kernel<<<grid, THREADS>>>(w, ls, out, n4);
}

// round 4
// speedup vs baseline: 1.3266x; 1.0833x over previous
#include <cuda_runtime.h>
#include <cuda_bf16.h>

#define THREADS      256
#define WARPS        (THREADS / 32)
#define ITERS        4
#define F4_PER_WI    64                      // float4 per warp-iteration (256 floats = 4 blocks)
#define F4_PER_CI    (WARPS * F4_PER_WI)     // 512 float4 per CTA-iteration
#define F4_PER_CTA   (F4_PER_CI * ITERS)     // 2048 float4 = 8192 floats per CTA

// Cell map: j = rne(v*16) + 16 in [0,32]  (cell width 1/16 = 0.0625 < min
// NF4-midpoint gap 0.0853 -> each cell holds at most one midpoint).
// Everything is a pure function of j (and the compare bit g):
//   thr_rep[j*32+lane]      = midpoint inside cell j (2.0f sentinel if none)
//   lvl_rep[(2j+g)*32+lane] = NF4[ b(j) + g ],  b(j) = #midpoints in cells < j
// idx = b(j) + (v > thr)  ==  searchsorted(mids, v, side=left)  exactly:
// the rne cell map is monotone, so cross-cell ordering is preserved; the
// in-cell case is a direct fp32 compare against the exact midpoint.
// Both tables are lane-replicated -> structurally conflict-free LDS (1 wf each).

template<bool GUARD>
__global__ __launch_bounds__(THREADS) void nf4_quant_kernel(
    const float4* __restrict__ w4,
    const float* __restrict__ log_scale,
    float4* __restrict__ o4,
    int n4, int f4_offset)
{
    __shared__ float thr_rep[33 * 32];
    __shared__ float lvl_rep[66 * 32];

    {
        const float nf4[16] = {
            -1.0f, -0.6961928f, -0.52507305f, -0.39491749f, -0.28444138f,
            -0.18477343f, -0.09105004f, 0.0f, 0.0795803f, 0.1609302f,
            0.2461123f, 0.33791524f, 0.44070983f, 0.562617f, 0.72295684f, 1.0f};

        for (int t = threadIdx.x; t < 33 * 32; t += THREADS) {
            int j = t >> 5;
            int b = 0; float thr = 2.0f; bool found = false;
            #pragma unroll
            for (int k = 0; k < 15; k++) {
                float mid = 0.5f * (nf4[k] + nf4[k + 1]);
                int jm = (int)(__float_as_uint(fmaf(mid, 16.0f, 8388624.0f)) & 0x3Fu);
                if (jm < j) b++;
                else if (jm == j) { thr = mid; found = true; }
            }
            thr_rep[t] = thr;
            int lane = t & 31;
            lvl_rep[(2 * j + 0) * 32 + lane] = nf4[b];
            lvl_rep[(2 * j + 1) * 32 + lane] = nf4[found ? b + 1 : b];
        }
    }
    __syncthreads();

    const float e = expf(__ldg(log_scale));
    const unsigned lane = threadIdx.x & 31u;
    const int      warp = threadIdx.x >> 5;
    const float* __restrict__ thr_lane = thr_rep + lane;
    const float* __restrict__ lvl_lane = lvl_rep + lane;

    // 8 lanes per 64-float block: lane owns float4 [blk*16 + p] and [blk*16 + 8 + p]
    const int p   = (int)(lane & 7u);
    const int blk = (int)(lane >> 3);
    const int toff = blk * 16 + p;

    const int base0 = f4_offset + blockIdx.x * F4_PER_CTA + warp * F4_PER_WI + toff;

    float4 a = make_float4(0.f, 0.f, 0.f, 0.f);
    float4 c = make_float4(0.f, 0.f, 0.f, 0.f);
    if (!GUARD || base0 < n4)     a = __ldcs(&w4[base0]);
    if (!GUARD || base0 + 8 < n4) c = __ldcs(&w4[base0 + 8]);

    #pragma unroll
    for (int i = 0; i < ITERS; i++) {
        const int idx = base0 + i * F4_PER_CI;

        float4 a2 = make_float4(0.f, 0.f, 0.f, 0.f);
        float4 c2 = make_float4(0.f, 0.f, 0.f, 0.f);
        if (i + 1 < ITERS) {
            int nidx = idx + F4_PER_CI;
            if (!GUARD || nidx < n4)     a2 = __ldcs(&w4[nidx]);
            if (!GUARD || nidx + 8 < n4) c2 = __ldcs(&w4[nidx + 8]);
        }

        // block absmax: 8 floats local, then 8-lane butterfly (stays in blk group)
        float m = fmaxf(fmaxf(fmaxf(fabsf(a.x), fabsf(a.y)), fmaxf(fabsf(a.z), fabsf(a.w))),
                        fmaxf(fmaxf(fabsf(c.x), fabsf(c.y)), fmaxf(fabsf(c.z), fabsf(c.w))));
        m = fmaxf(m, __shfl_xor_sync(0xffffffffu, m, 1));
        m = fmaxf(m, __shfl_xor_sync(0xffffffffu, m, 2));
        m = fmaxf(m, __shfl_xor_sync(0xffffffffu, m, 4));

        const float scale = fmaxf(m * e, 1e-6f);
        const float inv   = 1.0f / scale;

        float4 ra, rc;
        {
            float v, thr; unsigned j, g;
            #define Q(dst, src)                                                      \
                v   = fminf(fmaxf((src) * inv, -1.0f), 1.0f);                        \
                j   = __float_as_uint(fmaf(v, 16.0f, 8388624.0f)) & 0x3Fu;           \
                thr = thr_lane[j * 32u];                                             \
                g   = (v > thr) ? 1u : 0u;                                           \
                dst = lvl_lane[(2u * j + g) * 32u] * scale;
            Q(ra.x, a.x) Q(ra.y, a.y) Q(ra.z, a.z) Q(ra.w, a.w)
            Q(rc.x, c.x) Q(rc.y, c.y) Q(rc.z, c.z) Q(rc.w, c.w)
            #undef Q
        }

        if (!GUARD || idx < n4)     __stcs(&o4[idx], ra);
        if (!GUARD || idx + 8 < n4) __stcs(&o4[idx + 8], rc);

        a = a2; c = c2;
    }
}

extern "C" void kernel_launch(void* const* d_in, const int* in_sizes, int n_in,
                              void* d_out, int out_size)
{
    const float4* w4 = (const float4*)d_in[0];
    const float*  ls = (const float*)d_in[1];
    float4*       o4 = (float4*)d_out;

    const int n  = in_sizes[0];          // divisible by 64 (BLOCK)
    const int n4 = n >> 2;               // float4 count

    const int full = n4 / F4_PER_CTA;    // CTAs with no bounds checks needed
    const int rem  = n4 - full * F4_PER_CTA;

    if (full > 0)
        nf4_quant_kernel<false><<<full, THREADS>>>(w4, ls, o4, n4, 0);
    if (rem > 0) {
        const int gridr = (rem + F4_PER_CTA - 1) / F4_PER_CTA;
        nf4_quant_kernel<true><<<gridr, THREADS>>>(w4, ls, o4, n4, full * F4_PER_CTA);
    }
}